// round 1
// baseline (speedup 1.0000x reference)
#include <cuda_runtime.h>
#include <cuda_bf16.h>
#include <cstdint>
#include <cstddef>

// Problem constants (shapes fixed by the dataset)
#define RELS   16
#define INDIM  128
#define HDIM   128
#define ODIM   64
#define NMAX   50000

// Scratch (allocation-free rule: __device__ globals)
__device__ float g_t1[(size_t)NMAX * RELS * HDIM];   // [N, R, 128]  ~410MB
__device__ float g_h [(size_t)NMAX * HDIM];          // [N, 128]     ~25.6MB (fits L2)
__device__ float g_t2[(size_t)NMAX * RELS * ODIM];   // [N, R, 64]   ~205MB

// ---------------------------------------------------------------------------
// Zero kernel (d_out is poisoned; h accumulates atomics)
// ---------------------------------------------------------------------------
__global__ void zerok(float4* __restrict__ p, int n4) {
    int i = blockIdx.x * blockDim.x + threadIdx.x;
    if (i < n4) p[i] = make_float4(0.f, 0.f, 0.f, 0.f);
}

// ---------------------------------------------------------------------------
// Batched GEMM: T[n, r, 0:COLS] = act(A[n, 0:128]) @ W[r, 0:128, 0:COLS]
// Block = 128 rows x COLS cols, full K=128 resident in smem. 256 threads,
// each computes an 8 x (COLS/16) register micro-tile.
// ---------------------------------------------------------------------------
template <int COLS, bool RELU>
__global__ void rgcn_gemm(const float* __restrict__ A,
                          const float* __restrict__ W,
                          float* __restrict__ T,
                          int nrows) {
    extern __shared__ float sm[];
    float* As = sm;                    // [128][129] (pad 1 to kill bank conflicts)
    float* Bs = sm + 128 * 129;        // [128][COLS+4] (pad 4, keeps 16B align)
    constexpr int BSW = COLS + 4;
    constexpr int CPT = COLS / 16;     // cols per thread (8 or 4)

    const int r    = blockIdx.y;
    const int row0 = blockIdx.x * 128;
    const int tid  = threadIdx.x;

    // Load W[r] (fully) into smem, vectorized
    const float* Wr = W + (size_t)r * 128 * COLS;
    for (int i = tid; i < 128 * COLS / 4; i += 256) {
        int k = (i * 4) / COLS;
        int c = (i * 4) % COLS;
        float4 v = *(const float4*)(Wr + k * COLS + c);
        *(float4*)(Bs + k * BSW + c) = v;
    }
    // Load 128 A rows (optional fused ReLU for layer 2)
    for (int i = tid; i < 128 * 128 / 4; i += 256) {
        int rr = (i * 4) / 128;
        int k  = (i * 4) % 128;
        int grow = row0 + rr;
        float4 v = make_float4(0.f, 0.f, 0.f, 0.f);
        if (grow < nrows) v = *(const float4*)(A + (size_t)grow * 128 + k);
        if (RELU) {
            v.x = fmaxf(v.x, 0.f); v.y = fmaxf(v.y, 0.f);
            v.z = fmaxf(v.z, 0.f); v.w = fmaxf(v.w, 0.f);
        }
        float* a = As + rr * 129 + k;
        a[0] = v.x; a[1] = v.y; a[2] = v.z; a[3] = v.w;
    }
    __syncthreads();

    const int tx = tid & 15, ty = tid >> 4;
    const int arow = ty * 8;
    const int bcol = tx * CPT;

    float acc[8][CPT];
#pragma unroll
    for (int i = 0; i < 8; i++)
#pragma unroll
        for (int j = 0; j < CPT; j++) acc[i][j] = 0.f;

#pragma unroll 4
    for (int k = 0; k < 128; k++) {
        float a[8];
#pragma unroll
        for (int i = 0; i < 8; i++) a[i] = As[(arow + i) * 129 + k];
        float b[CPT];
#pragma unroll
        for (int j = 0; j < CPT; j += 4) {
            float4 bv = *(const float4*)(Bs + k * BSW + bcol + j);
            b[j] = bv.x; b[j + 1] = bv.y; b[j + 2] = bv.z; b[j + 3] = bv.w;
        }
#pragma unroll
        for (int i = 0; i < 8; i++)
#pragma unroll
            for (int j = 0; j < CPT; j++)
                acc[i][j] = fmaf(a[i], b[j], acc[i][j]);
    }

#pragma unroll
    for (int i = 0; i < 8; i++) {
        int grow = row0 + arow + i;
        if (grow < nrows) {
            float* o = T + ((size_t)grow * RELS + r) * COLS + bcol;
#pragma unroll
            for (int j = 0; j < CPT; j += 4) {
                *(float4*)(o + j) =
                    make_float4(acc[i][j], acc[i][j + 1], acc[i][j + 2], acc[i][j + 3]);
            }
        }
    }
}

// ---------------------------------------------------------------------------
// Edge scatter, layer 1: one warp per edge (128 floats).
// Reads 512B contiguous row t1[src, etype]; red.v4 into L2-resident h[dst].
// ---------------------------------------------------------------------------
__global__ void edge_scatter1(const float* __restrict__ t1, float* __restrict__ h,
                              const float* __restrict__ norm,
                              const int* __restrict__ src, const int* __restrict__ dst,
                              const int* __restrict__ ety, int E) {
    long long gt = (long long)blockIdx.x * blockDim.x + threadIdx.x;
    int e    = (int)(gt >> 5);
    int lane = threadIdx.x & 31;
    if (e >= E) return;
    int s = __ldg(src + e), d = __ldg(dst + e), r = __ldg(ety + e);
    float nm = __ldg(norm + e);
    float4 v = *(const float4*)(t1 + (((size_t)s * RELS + r) << 7) + lane * 4);
    v.x *= nm; v.y *= nm; v.z *= nm; v.w *= nm;
    float* o = h + ((size_t)d << 7) + lane * 4;
    asm volatile("red.global.add.v4.f32 [%0], {%1, %2, %3, %4};"
                 :: "l"(o), "f"(v.x), "f"(v.y), "f"(v.z), "f"(v.w) : "memory");
}

// ---------------------------------------------------------------------------
// Edge scatter, layer 2: half-warp per edge (64 floats), 2 edges per warp.
// ---------------------------------------------------------------------------
__global__ void edge_scatter2(const float* __restrict__ t2, float* __restrict__ out,
                              const float* __restrict__ norm,
                              const int* __restrict__ src, const int* __restrict__ dst,
                              const int* __restrict__ ety, int E) {
    long long gt = (long long)blockIdx.x * blockDim.x + threadIdx.x;
    int w    = (int)(gt >> 5);
    int lane = threadIdx.x & 31;
    int e    = w * 2 + (lane >> 4);
    if (e >= E) return;
    int l = lane & 15;
    int s = __ldg(src + e), d = __ldg(dst + e), r = __ldg(ety + e);
    float nm = __ldg(norm + e);
    float4 v = *(const float4*)(t2 + ((size_t)s * RELS + r) * ODIM + l * 4);
    v.x *= nm; v.y *= nm; v.z *= nm; v.w *= nm;
    float* o = out + (size_t)d * ODIM + l * 4;
    asm volatile("red.global.add.v4.f32 [%0], {%1, %2, %3, %4};"
                 :: "l"(o), "f"(v.x), "f"(v.y), "f"(v.z), "f"(v.w) : "memory");
}

// ---------------------------------------------------------------------------
// Launch. Inputs (metadata order): feat f32[N,128], norm f32[E,1],
// W1 f32[16,128,128], W2 f32[16,128,64], src i32[E], dst i32[E], etypes i32[E].
// Output: f32[N,64].
// ---------------------------------------------------------------------------
extern "C" void kernel_launch(void* const* d_in, const int* in_sizes, int n_in,
                              void* d_out, int out_size) {
    const float* feat = (const float*)d_in[0];
    const float* norm = (const float*)d_in[1];
    const float* W1   = (const float*)d_in[2];
    const float* W2   = (const float*)d_in[3];
    const int*   src  = (const int*)d_in[4];
    const int*   dst  = (const int*)d_in[5];
    const int*   ety  = (const int*)d_in[6];
    float* out = (float*)d_out;

    const int N = in_sizes[0] / INDIM;   // 50000
    const int E = in_sizes[4];           // 800000

    float *t1p, *t2p, *hp;
    cudaGetSymbolAddress((void**)&t1p, g_t1);
    cudaGetSymbolAddress((void**)&t2p, g_t2);
    cudaGetSymbolAddress((void**)&hp,  g_h);

    constexpr int SM1 = (128 * 129 + 128 * (128 + 4)) * (int)sizeof(float); // ~131KB
    constexpr int SM2 = (128 * 129 + 128 * (64 + 4))  * (int)sizeof(float); // ~99KB
    cudaFuncSetAttribute(rgcn_gemm<128, false>,
                         cudaFuncAttributeMaxDynamicSharedMemorySize, SM1);
    cudaFuncSetAttribute(rgcn_gemm<64, true>,
                         cudaFuncAttributeMaxDynamicSharedMemorySize, SM2);

    dim3 gg((N + 127) / 128, RELS);

    // Layer 1: t1 = feat @ W1[r]  ->  h[dst] += norm * t1[src, etype]
    {
        int n4 = N * HDIM / 4;
        zerok<<<(n4 + 255) / 256, 256>>>((float4*)hp, n4);
    }
    rgcn_gemm<128, false><<<gg, 256, SM1>>>(feat, W1, t1p, N);
    {
        long long threads = (long long)E * 32;
        int blocks = (int)((threads + 255) / 256);
        edge_scatter1<<<blocks, 256>>>(t1p, hp, norm, src, dst, ety, E);
    }

    // Layer 2: t2 = relu(h) @ W2[r]  ->  out[dst] += norm * t2[src, etype]
    rgcn_gemm<64, true><<<gg, 256, SM2>>>(hp, W2, t2p, N);
    {
        int n4 = N * ODIM / 4;
        zerok<<<(n4 + 255) / 256, 256>>>((float4*)out, n4);
    }
    {
        long long warps = ((long long)E + 1) / 2;
        long long threads = warps * 32;
        int blocks = (int)((threads + 255) / 256);
        edge_scatter2<<<blocks, 256>>>(t2p, out, norm, src, dst, ety, E);
    }
}

// round 3
// speedup vs baseline: 1.4168x; 1.4168x over previous
#include <cuda_runtime.h>
#include <cuda_bf16.h>
#include <cstdint>
#include <cstddef>

#define RELS   16
#define INDIM  128
#define HDIM   128
#define ODIM   64
#define NMAX   50000

// ---------------------------------------------------------------------------
// Scratch (__device__ globals; allocation-free rule)
// ---------------------------------------------------------------------------
__device__ float g_t1[(size_t)NMAX * RELS * HDIM];          // [N,R,128] ~410MB
__device__ float g_h [(size_t)NMAX * HDIM];                 // [N,128]   ~25.6MB
__device__ float g_t2[(size_t)NMAX * RELS * ODIM];          // [N,R,64]  ~205MB
__device__ __nv_bfloat16 g_ahi[(size_t)NMAX * 128];
__device__ __nv_bfloat16 g_alo[(size_t)NMAX * 128];
__device__ __nv_bfloat16 g_w1hi[RELS * 128 * 128];          // W1^T [r][n][k]
__device__ __nv_bfloat16 g_w1lo[RELS * 128 * 128];
__device__ __nv_bfloat16 g_w2hi[RELS * 64 * 128];           // W2^T [r][n][k]
__device__ __nv_bfloat16 g_w2lo[RELS * 64 * 128];

// ---------------------------------------------------------------------------
// Helpers (arch-agnostic PTX only: ldmatrix sm_75+, mma.bf16 sm_80+)
// ---------------------------------------------------------------------------
__device__ __forceinline__ uint32_t smem_u32(const void* p) {
    uint32_t a;
    asm("{ .reg .u64 t; cvta.to.shared.u64 t, %1; cvt.u32.u64 %0, t; }"
        : "=r"(a) : "l"(p));
    return a;
}
#define SWZ128(o) ((o) ^ (((o) >> 3) & 0x70))

__device__ __forceinline__ void ldsm4(uint32_t* r, uint32_t addr) {
    asm volatile("ldmatrix.sync.aligned.m8n8.x4.shared.b16 {%0,%1,%2,%3}, [%4];"
                 : "=r"(r[0]), "=r"(r[1]), "=r"(r[2]), "=r"(r[3]) : "r"(addr));
}
__device__ __forceinline__ void mma16816(float* d, const uint32_t* a, const uint32_t* b) {
    asm volatile("mma.sync.aligned.m16n8k16.row.col.f32.bf16.bf16.f32 "
                 "{%0,%1,%2,%3}, {%4,%5,%6,%7}, {%8,%9}, {%0,%1,%2,%3};"
                 : "+f"(d[0]), "+f"(d[1]), "+f"(d[2]), "+f"(d[3])
                 : "r"(a[0]), "r"(a[1]), "r"(a[2]), "r"(a[3]), "r"(b[0]), "r"(b[1]));
}

// ---------------------------------------------------------------------------
// Zero kernel
// ---------------------------------------------------------------------------
__global__ void zerok(float4* __restrict__ p, int n4) {
    int i = blockIdx.x * blockDim.x + threadIdx.x;
    if (i < n4) p[i] = make_float4(0.f, 0.f, 0.f, 0.f);
}

// ---------------------------------------------------------------------------
// Split fp32 -> (hi, lo) bf16 pair. Optional fused ReLU.
// ---------------------------------------------------------------------------
__global__ void splitA(const float* __restrict__ x, __nv_bfloat16* __restrict__ hi,
                       __nv_bfloat16* __restrict__ lo, int n, int relu) {
    for (int i = blockIdx.x * blockDim.x + threadIdx.x; i < n; i += gridDim.x * blockDim.x) {
        float v = x[i];
        if (relu) v = fmaxf(v, 0.f);
        __nv_bfloat16 h = __float2bfloat16(v);
        hi[i] = h;
        lo[i] = __float2bfloat16(v - __bfloat162float(h));
    }
}

// W [R][128][NC] -> Wt [R][NC][128] split into hi/lo bf16.
__global__ void splitW(const float* __restrict__ W, __nv_bfloat16* __restrict__ thi,
                       __nv_bfloat16* __restrict__ tlo, int NC) {
    int total = RELS * 128 * NC;
    for (int o = blockIdx.x * blockDim.x + threadIdx.x; o < total; o += gridDim.x * blockDim.x) {
        int r = o / (NC * 128);
        int rem = o - r * NC * 128;
        int n = rem / 128;
        int k = rem - n * 128;
        float v = W[((size_t)r * 128 + k) * NC + n];
        __nv_bfloat16 h = __float2bfloat16(v);
        thi[o] = h;
        tlo[o] = __float2bfloat16(v - __bfloat162float(h));
    }
}

// ---------------------------------------------------------------------------
// Tensor-core batched GEMM via mma.sync (bf16, 3-product split for fp32 acc).
// T[n, r, 0:COLS] = A[n, :] @ Wt[r]^T.  CTA: 128 rows x COLS, K=128.
// Smem tiles SW128-swizzled, split into two K=64 subtiles (128B rows).
// Warp tile: 32 x 64 (COLS=128) or 32 x 32 (COLS=64).
// ---------------------------------------------------------------------------
template <int COLS>
__global__ __launch_bounds__(256, 1)
void rgcn_mma_gemm(const __nv_bfloat16* __restrict__ Ahi, const __nv_bfloat16* __restrict__ Alo,
                   const __nv_bfloat16* __restrict__ Whi, const __nv_bfloat16* __restrict__ Wlo,
                   float* __restrict__ T, int nrows) {
    extern __shared__ char smem[];
    constexpr int ATILE = 128 * 128;      // bytes per K-subtile of A
    constexpr int BTILE = COLS * 128;     // bytes per K-subtile of B
    constexpr int A_HI = 0;
    constexpr int A_LO = 2 * ATILE;
    constexpr int B_HI = 4 * ATILE;
    constexpr int B_LO = B_HI + 2 * BTILE;
    constexpr int NW   = (COLS == 128) ? 64 : 32;   // warp n-extent
    constexpr int NF   = NW / 8;                    // n-frags per warp

    const uint32_t sb = smem_u32(smem);
    const int tid = threadIdx.x;
    const int wid = tid >> 5;
    const int lane = tid & 31;
    const int r = blockIdx.x;
    const int row0 = blockIdx.y * 128;

    // ---- load A (hi & lo), swizzled ----
    for (int i = tid; i < 128 * 16; i += 256) {
        int row = i >> 4, u = i & 15;
        uint32_t so = (u >> 3) * ATILE + SWZ128(row * 128 + (u & 7) * 16);
        int grow = row0 + row;
        uint4 vh = make_uint4(0, 0, 0, 0), vl = vh;
        if (grow < nrows) {
            vh = *(const uint4*)(Ahi + (size_t)grow * 128 + u * 8);
            vl = *(const uint4*)(Alo + (size_t)grow * 128 + u * 8);
        }
        *(uint4*)(smem + A_HI + so) = vh;
        *(uint4*)(smem + A_LO + so) = vl;
    }
    // ---- load B (hi & lo) for relation r ----
    for (int i = tid; i < COLS * 16; i += 256) {
        int n = i >> 4, u = i & 15;
        uint32_t so = (u >> 3) * BTILE + SWZ128(n * 128 + (u & 7) * 16);
        const size_t gi = ((size_t)r * COLS + n) * 128 + u * 8;
        *(uint4*)(smem + B_HI + so) = *(const uint4*)(Whi + gi);
        *(uint4*)(smem + B_LO + so) = *(const uint4*)(Wlo + gi);
    }
    __syncthreads();

    const int wm = wid & 3;       // m-group: rows wm*32 .. +31
    const int wn = wid >> 2;      // n-group: cols wn*NW .. +NW-1

    float acc[2][NF][4];
#pragma unroll
    for (int mf = 0; mf < 2; mf++)
#pragma unroll
        for (int nf = 0; nf < NF; nf++)
#pragma unroll
            for (int j = 0; j < 4; j++) acc[mf][nf][j] = 0.f;

    const int half = lane >> 4;           // 0/1 : low/high 8 k of the 16-k frag
    const int sr = lane & 15;             // sub-row within 16

    const int a_off[3] = {A_HI, A_HI, A_LO};
    const int b_off[3] = {B_HI, B_LO, B_HI};

#pragma unroll
    for (int p = 0; p < 3; p++) {
        const uint32_t abase = sb + a_off[p];
        const uint32_t bbase = sb + b_off[p];
#pragma unroll
        for (int ks = 0; ks < 8; ks++) {
            const int kt = ks >> 2;                 // K-subtile
            const int kb = (ks & 3) * 32;           // byte offset of 16-k within 128B row
            uint32_t a[2][4];
#pragma unroll
            for (int mf = 0; mf < 2; mf++) {
                int row = wm * 32 + mf * 16 + sr;
                uint32_t ad = abase + kt * ATILE + SWZ128(row * 128 + kb + half * 16);
                ldsm4(a[mf], ad);
            }
            uint32_t b[NF][2];
#pragma unroll
            for (int nq = 0; nq < NF / 2; nq++) {   // each ldsm4 covers 2 n-frags
                int n = wn * NW + nq * 16 + sr;
                uint32_t bd = bbase + kt * BTILE + SWZ128(n * 128 + kb + half * 16);
                uint32_t t[4];
                ldsm4(t, bd);
                b[nq * 2][0] = t[0]; b[nq * 2][1] = t[2];
                b[nq * 2 + 1][0] = t[1]; b[nq * 2 + 1][1] = t[3];
            }
#pragma unroll
            for (int mf = 0; mf < 2; mf++)
#pragma unroll
                for (int nf = 0; nf < NF; nf++)
                    mma16816(acc[mf][nf], a[mf], b[nf]);
        }
    }

    // ---- epilogue: direct fp32 stores ----
    const int mrow = lane >> 2;
    const int mcol = (lane & 3) * 2;
#pragma unroll
    for (int mf = 0; mf < 2; mf++) {
#pragma unroll
        for (int rr = 0; rr < 2; rr++) {            // rows +0 / +8
            int grow = row0 + wm * 32 + mf * 16 + mrow + rr * 8;
            if (grow < nrows) {
                float* o = T + ((size_t)grow * RELS + r) * COLS + wn * NW + mcol;
#pragma unroll
                for (int nf = 0; nf < NF; nf++) {
                    float2 v = make_float2(acc[mf][nf][rr * 2], acc[mf][nf][rr * 2 + 1]);
                    *(float2*)(o + nf * 8) = v;
                }
            }
        }
    }
}

// ---------------------------------------------------------------------------
// Edge scatter, layer 1: one warp per edge (128 floats).
// ---------------------------------------------------------------------------
__global__ void edge_scatter1(const float* __restrict__ t1, float* __restrict__ h,
                              const float* __restrict__ norm,
                              const int* __restrict__ src, const int* __restrict__ dst,
                              const int* __restrict__ ety, int E) {
    long long gt = (long long)blockIdx.x * blockDim.x + threadIdx.x;
    int e = (int)(gt >> 5);
    int lane = threadIdx.x & 31;
    if (e >= E) return;
    int s = __ldg(src + e), d = __ldg(dst + e), r = __ldg(ety + e);
    float nm = __ldg(norm + e);
    float4 v = *(const float4*)(t1 + (((size_t)s * RELS + r) << 7) + lane * 4);
    v.x *= nm; v.y *= nm; v.z *= nm; v.w *= nm;
    float* o = h + ((size_t)d << 7) + lane * 4;
    asm volatile("red.global.add.v4.f32 [%0], {%1, %2, %3, %4};"
                 :: "l"(o), "f"(v.x), "f"(v.y), "f"(v.z), "f"(v.w) : "memory");
}

// ---------------------------------------------------------------------------
// Edge scatter, layer 2: half-warp per edge (64 floats).
// ---------------------------------------------------------------------------
__global__ void edge_scatter2(const float* __restrict__ t2, float* __restrict__ out,
                              const float* __restrict__ norm,
                              const int* __restrict__ src, const int* __restrict__ dst,
                              const int* __restrict__ ety, int E) {
    long long gt = (long long)blockIdx.x * blockDim.x + threadIdx.x;
    int w = (int)(gt >> 5);
    int lane = threadIdx.x & 31;
    int e = w * 2 + (lane >> 4);
    if (e >= E) return;
    int l = lane & 15;
    int s = __ldg(src + e), d = __ldg(dst + e), r = __ldg(ety + e);
    float nm = __ldg(norm + e);
    float4 v = *(const float4*)(t2 + ((size_t)s * RELS + r) * ODIM + l * 4);
    v.x *= nm; v.y *= nm; v.z *= nm; v.w *= nm;
    float* o = out + (size_t)d * ODIM + l * 4;
    asm volatile("red.global.add.v4.f32 [%0], {%1, %2, %3, %4};"
                 :: "l"(o), "f"(v.x), "f"(v.y), "f"(v.z), "f"(v.w) : "memory");
}

// ---------------------------------------------------------------------------
// Launch
// ---------------------------------------------------------------------------
extern "C" void kernel_launch(void* const* d_in, const int* in_sizes, int n_in,
                              void* d_out, int out_size) {
    const float* feat = (const float*)d_in[0];
    const float* norm = (const float*)d_in[1];
    const float* W1   = (const float*)d_in[2];
    const float* W2   = (const float*)d_in[3];
    const int*   src  = (const int*)d_in[4];
    const int*   dst  = (const int*)d_in[5];
    const int*   ety  = (const int*)d_in[6];
    float* out = (float*)d_out;

    const int N = in_sizes[0] / INDIM;   // 50000
    const int E = in_sizes[4];           // 800000

    float *t1p, *t2p, *hp;
    __nv_bfloat16 *ahip, *alop, *w1hip, *w1lop, *w2hip, *w2lop;
    cudaGetSymbolAddress((void**)&t1p,  g_t1);
    cudaGetSymbolAddress((void**)&t2p,  g_t2);
    cudaGetSymbolAddress((void**)&hp,   g_h);
    cudaGetSymbolAddress((void**)&ahip, g_ahi);
    cudaGetSymbolAddress((void**)&alop, g_alo);
    cudaGetSymbolAddress((void**)&w1hip, g_w1hi);
    cudaGetSymbolAddress((void**)&w1lop, g_w1lo);
    cudaGetSymbolAddress((void**)&w2hip, g_w2hi);
    cudaGetSymbolAddress((void**)&w2lop, g_w2lo);

    constexpr int SM1 = 4 * 128 * 128 + 4 * 128 * 128;  // 131072 B
    constexpr int SM2 = 4 * 128 * 128 + 4 * 64 * 128;   // 98304 B
    cudaFuncSetAttribute(rgcn_mma_gemm<128>, cudaFuncAttributeMaxDynamicSharedMemorySize, SM1);
    cudaFuncSetAttribute(rgcn_mma_gemm<64>,  cudaFuncAttributeMaxDynamicSharedMemorySize, SM2);

    const int nb = (N + 127) / 128;
    dim3 gg(RELS, nb);

    // Weight splits (transposed to [r][n][k])
    splitW<<<(RELS * 128 * 128 + 255) / 256, 256>>>(W1, w1hip, w1lop, 128);
    splitW<<<(RELS * 128 * 64 + 255) / 256, 256>>>(W2, w2hip, w2lop, 64);

    // Layer 1
    {
        int g = (N * 128 + 255) / 256; if (g > 4096) g = 4096;
        splitA<<<g, 256>>>(feat, ahip, alop, N * 128, 0);
    }
    {
        int n4 = N * HDIM / 4;
        zerok<<<(n4 + 255) / 256, 256>>>((float4*)hp, n4);
    }
    rgcn_mma_gemm<128><<<gg, 256, SM1>>>(ahip, alop, w1hip, w1lop, t1p, N);
    {
        long long threads = (long long)E * 32;
        int blocks = (int)((threads + 255) / 256);
        edge_scatter1<<<blocks, 256>>>(t1p, hp, norm, src, dst, ety, E);
    }

    // Layer 2
    {
        int g = (N * 128 + 255) / 256; if (g > 4096) g = 4096;
        splitA<<<g, 256>>>(hp, ahip, alop, N * 128, 1);
    }
    rgcn_mma_gemm<64><<<gg, 256, SM2>>>(ahip, alop, w2hip, w2lop, t2p, N);
    {
        int n4 = N * ODIM / 4;
        zerok<<<(n4 + 255) / 256, 256>>>((float4*)out, n4);
    }
    {
        long long warps = ((long long)E + 1) / 2;
        long long threads = warps * 32;
        int blocks = (int)((threads + 255) / 256);
        edge_scatter2<<<blocks, 256>>>(t2p, out, norm, src, dst, ety, E);
    }
}

// round 7
// speedup vs baseline: 1.6860x; 1.1900x over previous
#include <cuda_runtime.h>
#include <cuda_bf16.h>
#include <cstdint>
#include <cstddef>

#define RELS   16
#define INDIM  128
#define HDIM   128
#define ODIM   64
#define NMAX   50000
#define EMAX   800000

// ---------------------------------------------------------------------------
// Scratch (__device__ globals; allocation-free rule)
// ---------------------------------------------------------------------------
__device__ float g_h[(size_t)NMAX * HDIM];                  // [N,128] ~25.6MB (L2)
__device__ __nv_bfloat16 g_w1hi[RELS * 128 * 128];          // W1^T [r][n][k]
__device__ __nv_bfloat16 g_w1lo[RELS * 128 * 128];
__device__ __nv_bfloat16 g_w2hi[RELS * 64 * 128];           // W2^T [r][n][k]
__device__ __nv_bfloat16 g_w2lo[RELS * 64 * 128];
__device__ int   g_hist[RELS];
__device__ int   g_reloff[RELS + 1];
__device__ int   g_blkoff[RELS + 1];
__device__ int   g_cursor[RELS];
__device__ int   g_srcp[EMAX];
__device__ int   g_dstp[EMAX];
__device__ float g_normp[EMAX];

// ---------------------------------------------------------------------------
// Helpers (arch-agnostic PTX: ldmatrix sm_75+, mma.bf16 sm_80+)
// ---------------------------------------------------------------------------
__device__ __forceinline__ uint32_t smem_u32(const void* p) {
    uint32_t a;
    asm("{ .reg .u64 t; cvta.to.shared.u64 t, %1; cvt.u32.u64 %0, t; }"
        : "=r"(a) : "l"(p));
    return a;
}
#define SWZ128(o) ((o) ^ (((o) >> 3) & 0x70))

__device__ __forceinline__ void ldsm4(uint32_t* r, uint32_t addr) {
    asm volatile("ldmatrix.sync.aligned.m8n8.x4.shared.b16 {%0,%1,%2,%3}, [%4];"
                 : "=r"(r[0]), "=r"(r[1]), "=r"(r[2]), "=r"(r[3]) : "r"(addr));
}
__device__ __forceinline__ void mma16816(float* d, const uint32_t* a, const uint32_t* b) {
    asm volatile("mma.sync.aligned.m16n8k16.row.col.f32.bf16.bf16.f32 "
                 "{%0,%1,%2,%3}, {%4,%5,%6,%7}, {%8,%9}, {%0,%1,%2,%3};"
                 : "+f"(d[0]), "+f"(d[1]), "+f"(d[2]), "+f"(d[3])
                 : "r"(a[0]), "r"(a[1]), "r"(a[2]), "r"(a[3]), "r"(b[0]), "r"(b[1]));
}
__device__ __forceinline__ uint32_t pack_bf16x2(float a, float b) {
    __nv_bfloat16 ha = __float2bfloat16(a), hb = __float2bfloat16(b);
    return (uint32_t)__bfloat16_as_ushort(ha) |
           ((uint32_t)__bfloat16_as_ushort(hb) << 16);
}

// ---------------------------------------------------------------------------
// Zero kernel
// ---------------------------------------------------------------------------
__global__ void zerok(float4* __restrict__ p, int n4) {
    int i = blockIdx.x * blockDim.x + threadIdx.x;
    if (i < n4) p[i] = make_float4(0.f, 0.f, 0.f, 0.f);
}

// ---------------------------------------------------------------------------
// W [R][128][NC] -> Wt [R][NC][128] split into hi/lo bf16.
// ---------------------------------------------------------------------------
__global__ void splitW(const float* __restrict__ W, __nv_bfloat16* __restrict__ thi,
                       __nv_bfloat16* __restrict__ tlo, int NC) {
    int total = RELS * 128 * NC;
    for (int o = blockIdx.x * blockDim.x + threadIdx.x; o < total; o += gridDim.x * blockDim.x) {
        int r = o / (NC * 128);
        int rem = o - r * NC * 128;
        int n = rem / 128;
        int k = rem - n * 128;
        float v = W[((size_t)r * 128 + k) * NC + n];
        __nv_bfloat16 h = __float2bfloat16(v);
        thi[o] = h;
        tlo[o] = __float2bfloat16(v - __bfloat162float(h));
    }
}

// ---------------------------------------------------------------------------
// Edge bucket sort by etype: hist -> scan -> permute
// ---------------------------------------------------------------------------
__global__ void zero_hist() {
    if (threadIdx.x < RELS) g_hist[threadIdx.x] = 0;
}
__global__ void histk(const int* __restrict__ ety, int E) {
    __shared__ int sh[RELS];
    if (threadIdx.x < RELS) sh[threadIdx.x] = 0;
    __syncthreads();
    int e = blockIdx.x * blockDim.x + threadIdx.x;
    if (e < E) atomicAdd(&sh[ety[e]], 1);
    __syncthreads();
    if (threadIdx.x < RELS) atomicAdd(&g_hist[threadIdx.x], sh[threadIdx.x]);
}
__global__ void scank() {
    int off = 0, boff = 0;
    for (int r = 0; r < RELS; r++) {
        g_reloff[r] = off; g_blkoff[r] = boff; g_cursor[r] = off;
        int c = g_hist[r];
        off += c; boff += (c + 127) / 128;
    }
    g_reloff[RELS] = off; g_blkoff[RELS] = boff;
}
__global__ void permutek(const int* __restrict__ src, const int* __restrict__ dst,
                         const int* __restrict__ ety, const float* __restrict__ norm, int E) {
    __shared__ int sh[RELS], sbase[RELS];
    if (threadIdx.x < RELS) sh[threadIdx.x] = 0;
    __syncthreads();
    int e = blockIdx.x * blockDim.x + threadIdx.x;
    int r = 0, lr = 0;
    if (e < E) { r = ety[e]; lr = atomicAdd(&sh[r], 1); }
    __syncthreads();
    if (threadIdx.x < RELS) sbase[threadIdx.x] = atomicAdd(&g_cursor[threadIdx.x], sh[threadIdx.x]);
    __syncthreads();
    if (e < E) {
        int pos = sbase[r] + lr;
        g_srcp[pos] = src[e];
        g_dstp[pos] = dst[e];
        g_normp[pos] = norm[e];
    }
}

// ---------------------------------------------------------------------------
// Fused gather + tensor-core GEMM + scatter.
// CTA = 128 edges of one relation. Gathers A[src] rows (fp32, converted in
// flight to hi/lo bf16), MMAs against W_r (3-product split, fp32 acc), stages
// results through smem, scales by norm, red.add.v4 into Out[dst].
// ---------------------------------------------------------------------------
template <int COLS, bool RELU>
__global__ __launch_bounds__(256)
void rgcn_fused(const float* __restrict__ A,
                const __nv_bfloat16* __restrict__ Whi, const __nv_bfloat16* __restrict__ Wlo,
                float* __restrict__ Out) {
    extern __shared__ char smem[];
    constexpr int ATILE = 128 * 128;      // bytes per K-subtile of A
    constexpr int BTILE = COLS * 128;     // bytes per K-subtile of B
    constexpr int A_HI = 0;
    constexpr int A_LO = 2 * ATILE;
    constexpr int B_HI = 4 * ATILE;
    constexpr int B_LO = B_HI + 2 * BTILE;
    constexpr int META = B_LO + 2 * BTILE;           // s_src,s_dst,s_norm
    constexpr int NW   = (COLS == 128) ? 64 : 32;
    constexpr int NF   = NW / 8;
    constexpr int STR  = COLS + 4;                   // staging stride (floats)
    constexpr int V4R  = COLS / 4;

    int* s_src = (int*)(smem + META);
    int* s_dst = (int*)(smem + META + 512);
    float* s_norm = (float*)(smem + META + 1024);
    float* stag = (float*)smem;                      // reuses A/B after MMA

    const uint32_t sb = smem_u32(smem);
    const int tid = threadIdx.x;
    const int wid = tid >> 5;
    const int lane = tid & 31;
    const int bid = blockIdx.x;

    // ---- map flat block -> (relation, edge tile) ----
    if (bid >= __ldg(&g_blkoff[RELS])) return;
    int r = 0;
#pragma unroll
    for (int i = 0; i < RELS; i++)
        if (bid >= __ldg(&g_blkoff[i + 1])) r = i + 1;
    const int e0 = __ldg(&g_reloff[r]) + (bid - __ldg(&g_blkoff[r])) * 128;
    const int nE = min(128, __ldg(&g_reloff[r + 1]) - e0);

    // ---- edge meta ----
    if (tid < 128) {
        bool v = tid < nE;
        s_src[tid] = v ? __ldg(&g_srcp[e0 + tid]) : 0;
        s_dst[tid] = v ? __ldg(&g_dstp[e0 + tid]) : 0;
        s_norm[tid] = v ? __ldg(&g_normp[e0 + tid]) : 0.f;
    }
    // ---- load W_r (pre-split hi/lo bf16), swizzled ----
    for (int i = tid; i < COLS * 16; i += 256) {
        int n = i >> 4, u = i & 15;
        uint32_t so = (u >> 3) * BTILE + SWZ128(n * 128 + (u & 7) * 16);
        const size_t gi = ((size_t)r * COLS + n) * 128 + u * 8;
        *(uint4*)(smem + B_HI + so) = *(const uint4*)(Whi + gi);
        *(uint4*)(smem + B_LO + so) = *(const uint4*)(Wlo + gi);
    }
    __syncthreads();   // s_src ready before gather

    // ---- gather A rows, convert fp32 -> hi/lo bf16, swizzled store ----
    for (int i = tid; i < 128 * 16; i += 256) {
        int row = i >> 4, u = i & 15;
        uint32_t so = (u >> 3) * ATILE + SWZ128(row * 128 + (u & 7) * 16);
        const float* ap = A + (size_t)s_src[row] * 128 + u * 8;
        float4 v0 = __ldg((const float4*)ap);
        float4 v1 = __ldg((const float4*)(ap + 4));
        float vs[8] = {v0.x, v0.y, v0.z, v0.w, v1.x, v1.y, v1.z, v1.w};
        if (RELU) {
#pragma unroll
            for (int j = 0; j < 8; j++) vs[j] = fmaxf(vs[j], 0.f);
        }
        uint32_t hi[4], lo[4];
#pragma unroll
        for (int j = 0; j < 4; j++) {
            float a = vs[2 * j], b = vs[2 * j + 1];
            __nv_bfloat16 ha = __float2bfloat16(a), hb = __float2bfloat16(b);
            float ra = a - __bfloat162float(ha), rb = b - __bfloat162float(hb);
            hi[j] = (uint32_t)__bfloat16_as_ushort(ha) |
                    ((uint32_t)__bfloat16_as_ushort(hb) << 16);
            lo[j] = pack_bf16x2(ra, rb);
        }
        *(uint4*)(smem + A_HI + so) = make_uint4(hi[0], hi[1], hi[2], hi[3]);
        *(uint4*)(smem + A_LO + so) = make_uint4(lo[0], lo[1], lo[2], lo[3]);
    }
    __syncthreads();

    // ---- MMA: 3-product bf16 split, fp32 accumulate ----
    const int wm = wid & 3;
    const int wn = wid >> 2;
    float acc[2][NF][4];
#pragma unroll
    for (int mf = 0; mf < 2; mf++)
#pragma unroll
        for (int nf = 0; nf < NF; nf++)
#pragma unroll
            for (int j = 0; j < 4; j++) acc[mf][nf][j] = 0.f;

    const int half = lane >> 4;
    const int sr = lane & 15;
    const int a_off[3] = {A_HI, A_HI, A_LO};
    const int b_off[3] = {B_HI, B_LO, B_HI};

#pragma unroll
    for (int p = 0; p < 3; p++) {
        const uint32_t abase = sb + a_off[p];
        const uint32_t bbase = sb + b_off[p];
#pragma unroll
        for (int ks = 0; ks < 8; ks++) {
            const int kt = ks >> 2;
            const int kb = (ks & 3) * 32;
            uint32_t a[2][4];
#pragma unroll
            for (int mf = 0; mf < 2; mf++) {
                int row = wm * 32 + mf * 16 + sr;
                ldsm4(a[mf], abase + kt * ATILE + SWZ128(row * 128 + kb + half * 16));
            }
            uint32_t b[NF][2];
#pragma unroll
            for (int nq = 0; nq < NF / 2; nq++) {
                int n = wn * NW + nq * 16 + sr;
                uint32_t t[4];
                ldsm4(t, bbase + kt * BTILE + SWZ128(n * 128 + kb + half * 16));
                b[nq * 2][0] = t[0]; b[nq * 2][1] = t[2];
                b[nq * 2 + 1][0] = t[1]; b[nq * 2 + 1][1] = t[3];
            }
#pragma unroll
            for (int mf = 0; mf < 2; mf++)
#pragma unroll
                for (int nf = 0; nf < NF; nf++)
                    mma16816(acc[mf][nf], a[mf], b[nf]);
        }
    }
    __syncthreads();   // A/B tiles dead; reuse as staging

    // ---- stage fp32 result into smem (conflict-free, padded stride) ----
    const int mrow = lane >> 2;
    const int mcol = (lane & 3) * 2;
#pragma unroll
    for (int mf = 0; mf < 2; mf++)
#pragma unroll
        for (int rr = 0; rr < 2; rr++) {
            int lrow = wm * 32 + mf * 16 + mrow + rr * 8;
            float* o = stag + lrow * STR + wn * NW + mcol;
#pragma unroll
            for (int nf = 0; nf < NF; nf++)
                *(float2*)(o + nf * 8) =
                    make_float2(acc[mf][nf][rr * 2], acc[mf][nf][rr * 2 + 1]);
        }
    __syncthreads();

    // ---- scale by norm, red.add.v4 into Out[dst] ----
    for (int idx = tid; idx < 128 * V4R; idx += 256) {
        int row = idx / V4R, c4 = idx % V4R;
        if (row < nE) {
            float4 v = *(float4*)(stag + row * STR + c4 * 4);
            float nm = s_norm[row];
            v.x *= nm; v.y *= nm; v.z *= nm; v.w *= nm;
            float* o = Out + (size_t)s_dst[row] * COLS + c4 * 4;
            asm volatile("red.global.add.v4.f32 [%0], {%1, %2, %3, %4};"
                         :: "l"(o), "f"(v.x), "f"(v.y), "f"(v.z), "f"(v.w) : "memory");
        }
    }
}

// ---------------------------------------------------------------------------
// Launch
// ---------------------------------------------------------------------------
extern "C" void kernel_launch(void* const* d_in, const int* in_sizes, int n_in,
                              void* d_out, int out_size) {
    const float* feat = (const float*)d_in[0];
    const float* norm = (const float*)d_in[1];
    const float* W1   = (const float*)d_in[2];
    const float* W2   = (const float*)d_in[3];
    const int*   src  = (const int*)d_in[4];
    const int*   dst  = (const int*)d_in[5];
    const int*   ety  = (const int*)d_in[6];
    float* out = (float*)d_out;

    const int N = in_sizes[0] / INDIM;   // 50000
    const int E = in_sizes[4];           // 800000

    float* hp;
    __nv_bfloat16 *w1hip, *w1lop, *w2hip, *w2lop;
    cudaGetSymbolAddress((void**)&hp,    g_h);
    cudaGetSymbolAddress((void**)&w1hip, g_w1hi);
    cudaGetSymbolAddress((void**)&w1lop, g_w1lo);
    cudaGetSymbolAddress((void**)&w2hip, g_w2hi);
    cudaGetSymbolAddress((void**)&w2lop, g_w2lo);

    // smem: A(64K) + B(2*BTILE*2) + meta(1.5K)
    constexpr int SM1 = 4 * 128 * 128 + 4 * 128 * 128 + 1536; // 132608
    constexpr int SM2 = 4 * 128 * 128 + 4 * 64 * 128 + 1536;  // 99840
    cudaFuncSetAttribute(rgcn_fused<128, false>,
                         cudaFuncAttributeMaxDynamicSharedMemorySize, SM1);
    cudaFuncSetAttribute(rgcn_fused<64, true>,
                         cudaFuncAttributeMaxDynamicSharedMemorySize, SM2);

    // Weight splits (transposed to [r][n][k])
    splitW<<<(RELS * 128 * 128 + 255) / 256, 256>>>(W1, w1hip, w1lop, 128);
    splitW<<<(RELS * 128 * 64 + 255) / 256, 256>>>(W2, w2hip, w2lop, 64);

    // Edge bucket sort by etype
    const int eb = (E + 255) / 256;
    zero_hist<<<1, 32>>>();
    histk<<<eb, 256>>>(ety, E);
    scank<<<1, 1>>>();
    permutek<<<eb, 256>>>(src, dst, ety, norm, E);

    const int gB = (E + 127) / 128 + RELS;   // upper bound on sum of per-rel blocks

    // Layer 1: h[dst] += norm * (feat[src] @ W1[etype])
    {
        int n4 = N * HDIM / 4;
        zerok<<<(n4 + 255) / 256, 256>>>((float4*)hp, n4);
    }
    rgcn_fused<128, false><<<gB, 256, SM1>>>(feat, w1hip, w1lop, hp);

    // Layer 2: out[dst] += norm * (relu(h)[src] @ W2[etype])
    {
        int n4 = N * ODIM / 4;
        zerok<<<(n4 + 255) / 256, 256>>>((float4*)out, n4);
    }
    rgcn_fused<64, true><<<gB, 256, SM2>>>(hp, w2hip, w2lop, out);
}